// round 13
// baseline (speedup 1.0000x reference)
#include <cuda_runtime.h>
#include <cuda_fp16.h>
#include <cstdint>

typedef unsigned long long ull;

#define KD 64
#define NPTS 8192
#define SEG 2048
#define ASZ 32768          // one 128x128-fp16 operand tile in frag layout

// ---------------- scratch (__device__ globals; no allocation) ----------------
__device__ float g_norms[NPTS];
__device__ uint4 g_Abuf[32 * 2048];     // goal tiles:  [mblock][mf8][ks8][lane32] uint4
__device__ uint2 g_Bbuf[64 * 4096];     // feat tiles:  [tile][nf16][ks8][lane32] uint2
__device__ int g_cand[4096 * 64];       // top-4 per (goal, split, strip): 8*2*4
__device__ ull g_kA[NPTS], g_kB[NPTS];
__device__ int g_rA[NPTS], g_rB[NPTS];
__device__ int g_perm[NPTS];

// ---------------- threefry2x32 (exact JAX, partitionable) ----------------
__device__ __forceinline__ void tf2x32(unsigned k0, unsigned k1,
                                       unsigned c0, unsigned c1,
                                       unsigned &o0, unsigned &o1) {
    unsigned ks2 = k0 ^ k1 ^ 0x1BD11BDAu;
    unsigned x0 = c0 + k0, x1 = c1 + k1;
#define TF_RND(r) { x0 += x1; x1 = (x1 << (r)) | (x1 >> (32 - (r))); x1 ^= x0; }
    TF_RND(13) TF_RND(15) TF_RND(26) TF_RND(6)   x0 += k1;  x1 += ks2 + 1u;
    TF_RND(17) TF_RND(29) TF_RND(16) TF_RND(24)  x0 += ks2; x1 += k0 + 2u;
    TF_RND(13) TF_RND(15) TF_RND(26) TF_RND(6)   x0 += k0;  x1 += k1 + 3u;
    TF_RND(17) TF_RND(29) TF_RND(16) TF_RND(24)  x0 += k1;  x1 += ks2 + 4u;
    TF_RND(13) TF_RND(15) TF_RND(26) TF_RND(6)   x0 += ks2; x1 += k0 + 5u;
#undef TF_RND
    o0 = x0; o1 = x1;
}

__global__ void keys_k() {
    int i = blockIdx.x * blockDim.x + threadIdx.x;
    if (i >= NPTS) return;
    unsigned n0, n1, s10, s11, s20, s21, lo, hi;
    tf2x32(0u, 42u, 0u, 0u, n0, n1);
    tf2x32(0u, 42u, 0u, 1u, s10, s11);
    tf2x32(n0, n1, 0u, 1u, s20, s21);
    tf2x32(s10, s11, 0u, (unsigned)i, lo, hi);
    g_kA[i] = ((ull)(lo ^ hi) << 32) | (unsigned)i;
    tf2x32(s20, s21, 0u, (unsigned)i, lo, hi);
    g_kB[i] = ((ull)(lo ^ hi) << 32) | (unsigned)i;
    g_rA[i] = 0; g_rB[i] = 0;
}

__global__ __launch_bounds__(256) void rank_k() {
    __shared__ ull tile[SEG];
    const ull* K = blockIdx.y ? g_kB : g_kA;
    int* R = blockIdx.y ? g_rB : g_rA;
    int i = blockIdx.x * 256 + threadIdx.x;
    int base = blockIdx.z * SEG;
    ull my = K[i];
    for (int j = threadIdx.x; j < SEG; j += 256) tile[j] = K[base + j];
    __syncthreads();
    int cnt = 0;
#pragma unroll 8
    for (int j = 0; j < SEG; j++) cnt += (tile[j] < my);
    atomicAdd(&R[i], cnt);
}

__global__ void compose_k() {
    int i = blockIdx.x * blockDim.x + threadIdx.x;
    if (i >= NPTS) return;
    g_perm[g_rB[g_rA[i]]] = i;
}

// ---------------- fp16 split helpers ----------------
__device__ __forceinline__ float hi_f(float v) {
    return __half2float(__float2half_rn(v));
}
__device__ __forceinline__ unsigned packh2(float a, float b) {
    __half2 h = __halves2half2(__float2half_rn(a), __float2half_rn(b));
    return *reinterpret_cast<unsigned*>(&h);
}
__device__ __forceinline__ unsigned a_pair(const float* row, int k) {
    int kk = k & 63;
    float v0 = row[kk], v1 = row[kk + 1];
    if (k >= 64) { v0 -= hi_f(v0); v1 -= hi_f(v1); }
    return packh2(-2.f * hi_f(v0), -2.f * hi_f(v1));
}
__device__ __forceinline__ unsigned b_pair(const float* row, int k) {
    int kk = k & 63;
    return packh2(hi_f(row[kk]), hi_f(row[kk + 1]));
}

// prep B + norms: stage 128 rows coalesced into smem, then pack frags + exact norms.
__global__ __launch_bounds__(256) void prep_feats(const float* __restrict__ rowsBase,
                                                  int tileBase, int rowBase) {
    __shared__ float stage[128 * KD];
    const float4* bsrc = (const float4*)rowsBase + (size_t)blockIdx.x * 2048;
    float4* st4 = (float4*)stage;
#pragma unroll
    for (int i = 0; i < 8; i++)
        st4[threadIdx.x + 256 * i] = bsrc[threadIdx.x + 256 * i];
    __syncthreads();

    if (threadIdx.x < 128) {
        const float* r = stage + threadIdx.x * KD;
        float s = 0.f;
#pragma unroll
        for (int k = 0; k < KD; k++)
            s = __fadd_rn(s, __fmul_rn(r[k], r[k]));
        g_norms[rowBase + blockIdx.x * 128 + threadIdx.x] = s;
    }

    uint2* dst = g_Bbuf + (size_t)(tileBase + blockIdx.x) * 4096;
#pragma unroll
    for (int i = 0; i < 16; i++) {
        int e = threadIdx.x + 256 * i;
        int nf = e >> 8, ks = (e >> 5) & 7, lane = e & 31;
        const float* row = stage + (size_t)(nf * 8 + (lane >> 2)) * KD;
        int k0 = ks * 16 + (lane & 3) * 2;
        uint2 o;
        o.x = b_pair(row, k0);
        o.y = b_pair(row, k0 + 8);
        dst[e] = o;
    }
}

// prep A: gather 128 goal rows (optionally via perm) into smem, pack frags.
__global__ __launch_bounds__(256) void prep_goals(const float* __restrict__ rows,
                                                  int usePerm) {
    __shared__ float stage[128 * KD];
    int gbase = blockIdx.x * 128;
    float4* st4 = (float4*)stage;
#pragma unroll
    for (int i = 0; i < 8; i++) {
        int e = threadIdx.x + 256 * i;
        int r = e >> 4, q = e & 15;
        int src = usePerm ? g_perm[gbase + r] : (gbase + r);
        st4[e] = ((const float4*)(rows + (size_t)src * KD))[q];
    }
    __syncthreads();

    uint4* dst = g_Abuf + blockIdx.x * 2048;
#pragma unroll
    for (int i = 0; i < 8; i++) {
        int e = threadIdx.x + 256 * i;
        int mf = e >> 8, ks = (e >> 5) & 7, lane = e & 31;
        int rloc = mf * 16 + (lane >> 2);
        int k0 = ks * 16 + (lane & 3) * 2;
        const float* r0 = stage + (size_t)rloc * KD;
        const float* r1 = stage + (size_t)(rloc + 8) * KD;
        uint4 o;
        o.x = a_pair(r0, k0);     o.y = a_pair(r1, k0);
        o.z = a_pair(r0, k0 + 8); o.w = a_pair(r1, k0 + 8);
        dst[e] = o;
    }
}

// ---------------- low-level helpers ----------------
__device__ __forceinline__ unsigned smem_u32(const void* p) {
    unsigned a;
    asm("{ .reg .u64 t; cvta.to.shared.u64 t, %1; cvt.u32.u64 %0, t; }"
        : "=r"(a) : "l"(p));
    return a;
}
__device__ __forceinline__ void cp_async16(unsigned s, const void* g) {
    asm volatile("cp.async.cg.shared.global [%0], [%1], 16;" :: "r"(s), "l"(g));
}
__device__ __forceinline__ void cp_commit() {
    asm volatile("cp.async.commit_group;" ::: "memory");
}
__device__ __forceinline__ void cp_wait0() {
    asm volatile("cp.async.wait_group 0;" ::: "memory");
}
__device__ __forceinline__ void cp_wait1() {
    asm volatile("cp.async.wait_group 1;" ::: "memory");
}
__device__ __forceinline__ void mma16816(float* d, uint4 a, uint2 b) {
    asm volatile(
        "mma.sync.aligned.m16n8k16.row.col.f32.f16.f16.f32 "
        "{%0,%1,%2,%3}, {%4,%5,%6,%7}, {%8,%9}, {%0,%1,%2,%3};"
        : "+f"(d[0]), "+f"(d[1]), "+f"(d[2]), "+f"(d[3])
        : "r"(a.x), "r"(a.y), "r"(a.z), "r"(a.w), "r"(b.x), "r"(b.y));
}
__device__ __forceinline__ unsigned fkey(float f) {
    unsigned u = __float_as_uint(f);
    return (u & 0x80000000u) ? ~u : (u | 0x80000000u);
}
__device__ __forceinline__ void top3_ins(float v, int idx, float* bv, int* bi) {
    if (v < bv[2]) {
        if (v < bv[1]) {
            bv[2] = bv[1]; bi[2] = bi[1];
            if (v < bv[0]) {
                bv[1] = bv[0]; bi[1] = bi[0];
                bv[0] = v; bi[0] = idx;
            } else { bv[1] = v; bi[1] = idx; }
        } else { bv[2] = v; bi[2] = idx; }
    }
}

__device__ __forceinline__ void issue_tile(unsigned sB, unsigned sN,
                                           int tileIdx, int buf, int tid) {
    const uint4* src = (const uint4*)(g_Bbuf + (size_t)tileIdx * 4096);
    unsigned d = sB + (unsigned)buf * ASZ;
#pragma unroll
    for (int j = 0; j < 8; j++)
        cp_async16(d + (unsigned)(tid + 256 * j) * 16, src + tid + 256 * j);
    if (tid < 32)
        cp_async16(sN + (unsigned)buf * 512 + tid * 16,
                   &g_norms[tileIdx * 128 + tid * 4]);
}

// ---------------- HMMA KNN: single-pass acc, guarded epilogue --------------------
// grid (32 m-blocks, 8 splits); block 256 = 8 warps (4m x 2n).
// Warp (wm,wn): goals [wm*32,+32), feats strip [wn*64,+64). Single pass over all
// 8 n-frags per ks (A frags loaded ONCE per tile). Epilogue insert is guarded by a
// fminf so the common no-candidate case costs ~4 ops per quad.
__global__ __launch_bounds__(256, 2) void mma_knn(int T) {
    extern __shared__ char smem[];
    char* A_s = smem;
    char* B_s = smem + ASZ;
    float* Ns = (float*)(smem + 3 * ASZ);
    unsigned sB = smem_u32(B_s), sN = smem_u32(Ns);
    int tid = threadIdx.x, lane = tid & 31, w = tid >> 5;
    int wm = w & 3, wn = w >> 2;
    int mb = blockIdx.x, split = blockIdx.y;

    {
        const uint4* Asrc = g_Abuf + mb * 2048;
        unsigned sA = smem_u32(A_s);
#pragma unroll
        for (int j = 0; j < 8; j++)
            cp_async16(sA + (unsigned)(tid + 256 * j) * 16, Asrc + tid + 256 * j);
        issue_tile(sB, sN, split * T + 0, 0, tid);
        cp_commit();
        issue_tile(sB, sN, split * T + 1, 1, tid);
        cp_commit();
    }

    float bv[4][3]; int bi[4][3];
#pragma unroll
    for (int r = 0; r < 4; r++)
#pragma unroll
        for (int t = 0; t < 3; t++) { bv[r][t] = 3.402823466e38f; bi[r][t] = 0; }

    for (int t = 0; t < T; t++) {
        if (t < T - 1) cp_wait1(); else cp_wait0();
        __syncthreads();

        const uint4* Af = (const uint4*)A_s;
        const uint2* Bf = (const uint2*)(B_s + (t & 1) * ASZ);
        const float* fn = Ns + (t & 1) * 128;
        int tileIdx = split * T + t;

        float acc[2][8][4];
#pragma unroll
        for (int i = 0; i < 2; i++)
#pragma unroll
            for (int q = 0; q < 8; q++)
#pragma unroll
                for (int e = 0; e < 4; e++) acc[i][q][e] = 0.f;

#pragma unroll
        for (int ks = 0; ks < 8; ks++) {
            uint4 a0 = Af[((wm * 2 + 0) * 8 + ks) * 32 + lane];
            uint4 a1 = Af[((wm * 2 + 1) * 8 + ks) * 32 + lane];
#pragma unroll
            for (int q = 0; q < 8; q++) {
                uint2 b = Bf[((wn * 8 + q) * 8 + ks) * 32 + lane];
                mma16816(acc[0][q], a0, b);
                mma16816(acc[1][q], a1, b);
            }
        }

#pragma unroll
        for (int i = 0; i < 2; i++)
#pragma unroll
            for (int q = 0; q < 8; q++) {
                int cb = wn * 64 + q * 8 + (lane & 3) * 2;
                float2 f2 = *(const float2*)(fn + cb);
                int gidx = tileIdx * 128 + cb;
                float d0 = acc[i][q][0] + f2.x, d1 = acc[i][q][1] + f2.y;
                if (fminf(d0, d1) < bv[i*2][2]) {
                    top3_ins(d0, gidx,     bv[i*2], bi[i*2]);
                    top3_ins(d1, gidx + 1, bv[i*2], bi[i*2]);
                }
                float d2 = acc[i][q][2] + f2.x, d3 = acc[i][q][3] + f2.y;
                if (fminf(d2, d3) < bv[i*2+1][2]) {
                    top3_ins(d2, gidx,     bv[i*2+1], bi[i*2+1]);
                    top3_ins(d3, gidx + 1, bv[i*2+1], bi[i*2+1]);
                }
            }
        __syncthreads();
        if (t + 2 < T) {
            issue_tile(sB, sN, split * T + t + 2, t & 1, tid);
            cp_commit();
        }
    }

    // quad merge: 12 candidates per goal row -> top-4, slot keyed by (split, wn)
#pragma unroll
    for (int rr = 0; rr < 4; rr++) {
        ull cand[3];
#pragma unroll
        for (int t3 = 0; t3 < 3; t3++)
            cand[t3] = ((ull)fkey(bv[rr][t3]) << 32) | (unsigned)bi[rr][t3];
        int pos = 0;
        int goal = mb * 128 + wm * 32 + (rr >> 1) * 16 + (rr & 1) * 8 + (lane >> 2);
#pragma unroll
        for (int t4 = 0; t4 < 4; t4++) {
            ull cur = (pos < 3) ? cand[pos] : ~0ull;
            ull m = cur;
            ull o1 = __shfl_xor_sync(0xffffffffu, m, 1); if (o1 < m) m = o1;
            ull o2 = __shfl_xor_sync(0xffffffffu, m, 2); if (o2 < m) m = o2;
            if (cur == m) pos++;
            if ((lane & 3) == 0)
                g_cand[goal * 64 + (split * 2 + wn) * 4 + t4] =
                    (int)(m & 0xffffffffu);
        }
    }
}

// ---------------- exact rescore: fp32 d2 over 64 candidates, top-3, mean ---------
__global__ void rescore_k(const float* __restrict__ rows, int usePerm,
                          float* __restrict__ outp) {
    __shared__ float gr[8][64];
    int w = threadIdx.x >> 5, lane = threadIdx.x & 31;
    int g = blockIdx.x * 8 + w;
    int gsrc = usePerm ? g_perm[g] : g;
    const float* grow = rows + (size_t)gsrc * KD;
    gr[w][lane] = grow[lane];
    gr[w][lane + 32] = grow[lane + 32];
    __syncwarp();
    float gn = g_norms[gsrc];

    ull key[2];
#pragma unroll
    for (int ci = 0; ci < 2; ci++) {
        int cand = g_cand[g * 64 + ci * 32 + lane];
        const float4* f4 = (const float4*)(rows + (size_t)cand * KD);
        float dot = 0.f;
#pragma unroll
        for (int k4 = 0; k4 < 16; k4++) {
            float4 v = f4[k4];
            dot = fmaf(gr[w][k4 * 4 + 0], v.x, dot);
            dot = fmaf(gr[w][k4 * 4 + 1], v.y, dot);
            dot = fmaf(gr[w][k4 * 4 + 2], v.z, dot);
            dot = fmaf(gr[w][k4 * 4 + 3], v.w, dot);
        }
        float d2 = fmaf(-2.f, dot, gn + g_norms[cand]);
        key[ci] = ((ull)fkey(d2) << 32) | (unsigned)cand;
    }
    if (key[1] < key[0]) { ull tmp = key[0]; key[0] = key[1]; key[1] = tmp; }

    int ids[3]; int pos = 0;
#pragma unroll
    for (int t = 0; t < 3; t++) {
        ull cur = (pos == 0) ? key[0] : ((pos == 1) ? key[1] : ~0ull);
        ull m = cur;
        for (int off = 16; off; off >>= 1) {
            ull o = __shfl_xor_sync(0xffffffffu, m, off);
            if (o < m) m = o;
        }
        if (cur == m) pos++;
        ids[t] = (int)(m & 0xffffffffu);
    }
    const float* r0 = rows + (size_t)ids[0] * KD;
    const float* r1 = rows + (size_t)ids[1] * KD;
    const float* r2 = rows + (size_t)ids[2] * KD;
#pragma unroll
    for (int d = lane; d < KD; d += 32)
        outp[(size_t)g * KD + d] = ((r0[d] + r1[d]) + r2[d]) / 3.0f;
}

// ---------------- orchestration ----------------
extern "C" void kernel_launch(void* const* d_in, const int* in_sizes, int n_in,
                              void* d_out, int out_size) {
    const float* x = (const float*)d_in[0];   // [4096, 64]
    float* out = (float*)d_out;               // [12288, 64]

    const int MMA_SMEM = 3 * ASZ + 1024;      // 99328
    cudaFuncSetAttribute(mma_knn, cudaFuncAttributeMaxDynamicSharedMemorySize,
                         MMA_SMEM);

    cudaMemcpyAsync(out, x, (size_t)4096 * KD * sizeof(float),
                    cudaMemcpyDeviceToDevice);

    // ---- step 1: goals = feats = rows 0..4095 (8 splits x 4 tiles) ----
    prep_feats<<<32, 256>>>(out, 0, 0);                           // 1 (+ norms)
    prep_goals<<<32, 256>>>(out, 0);                              // 2
    keys_k<<<NPTS / 512, 512>>>();                                // 3 (indep)
    mma_knn<<<dim3(32, 8), 256, MMA_SMEM>>>(4);                   // 4 (ncu slot)
    rank_k<<<dim3(NPTS / 256, 2, NPTS / SEG), 256>>>();           // 5
    compose_k<<<NPTS / 512, 512>>>();                             // 6
    rescore_k<<<512, 256>>>(out, 0, out + (size_t)4096 * KD);     // 7

    // ---- step 2: feats = rows 0..8191 (8 splits x 8 tiles), goals = perm ----
    prep_feats<<<32, 256>>>(out + (size_t)4096 * KD, 32, 4096);
    prep_goals<<<32, 256>>>(out, 1);
    mma_knn<<<dim3(32, 8), 256, MMA_SMEM>>>(8);
    rescore_k<<<512, 256>>>(out, 1, out + (size_t)8192 * KD);
}

// round 14
// speedup vs baseline: 1.1029x; 1.1029x over previous
#include <cuda_runtime.h>
#include <cuda_fp16.h>
#include <cstdint>

typedef unsigned long long ull;

#define KD 64
#define NPTS 8192
#define SEG 2048
#define ASZ 16384          // one 128x64-fp16 operand tile in frag layout

// ---------------- scratch (__device__ globals; no allocation) ----------------
__device__ float g_norms[NPTS];
__device__ uint4 g_Abuf[32 * 1024];     // goal tiles:  [mblock][mf8][ks4][lane32] uint4
__device__ uint2 g_Bbuf[64 * 2048];     // feat tiles:  [tile][nf16][ks4][lane32] uint2
__device__ int g_cand[4096 * 64];       // top-4 per (goal, split, strip): 8*2*4
__device__ ull g_kA[NPTS], g_kB[NPTS];
__device__ int g_rA[NPTS], g_rB[NPTS];
__device__ int g_perm[NPTS];

// ---------------- threefry2x32 (exact JAX, partitionable) ----------------
__device__ __forceinline__ void tf2x32(unsigned k0, unsigned k1,
                                       unsigned c0, unsigned c1,
                                       unsigned &o0, unsigned &o1) {
    unsigned ks2 = k0 ^ k1 ^ 0x1BD11BDAu;
    unsigned x0 = c0 + k0, x1 = c1 + k1;
#define TF_RND(r) { x0 += x1; x1 = (x1 << (r)) | (x1 >> (32 - (r))); x1 ^= x0; }
    TF_RND(13) TF_RND(15) TF_RND(26) TF_RND(6)   x0 += k1;  x1 += ks2 + 1u;
    TF_RND(17) TF_RND(29) TF_RND(16) TF_RND(24)  x0 += ks2; x1 += k0 + 2u;
    TF_RND(13) TF_RND(15) TF_RND(26) TF_RND(6)   x0 += k0;  x1 += k1 + 3u;
    TF_RND(17) TF_RND(29) TF_RND(16) TF_RND(24)  x0 += k1;  x1 += ks2 + 4u;
    TF_RND(13) TF_RND(15) TF_RND(26) TF_RND(6)   x0 += ks2; x1 += k0 + 5u;
#undef TF_RND
    o0 = x0; o1 = x1;
}

__global__ void keys_k() {
    int i = blockIdx.x * blockDim.x + threadIdx.x;
    if (i >= NPTS) return;
    unsigned n0, n1, s10, s11, s20, s21, lo, hi;
    tf2x32(0u, 42u, 0u, 0u, n0, n1);
    tf2x32(0u, 42u, 0u, 1u, s10, s11);
    tf2x32(n0, n1, 0u, 1u, s20, s21);
    tf2x32(s10, s11, 0u, (unsigned)i, lo, hi);
    g_kA[i] = ((ull)(lo ^ hi) << 32) | (unsigned)i;
    tf2x32(s20, s21, 0u, (unsigned)i, lo, hi);
    g_kB[i] = ((ull)(lo ^ hi) << 32) | (unsigned)i;
    g_rA[i] = 0; g_rB[i] = 0;
}

__global__ __launch_bounds__(256) void rank_k() {
    __shared__ ull tile[SEG];
    const ull* K = blockIdx.y ? g_kB : g_kA;
    int* R = blockIdx.y ? g_rB : g_rA;
    int i = blockIdx.x * 256 + threadIdx.x;
    int base = blockIdx.z * SEG;
    ull my = K[i];
    for (int j = threadIdx.x; j < SEG; j += 256) tile[j] = K[base + j];
    __syncthreads();
    int cnt = 0;
#pragma unroll 8
    for (int j = 0; j < SEG; j++) cnt += (tile[j] < my);
    atomicAdd(&R[i], cnt);
}

__global__ void compose_k() {
    int i = blockIdx.x * blockDim.x + threadIdx.x;
    if (i >= NPTS) return;
    g_perm[g_rB[g_rA[i]]] = i;
}

// ---------------- fp16 helpers ----------------
__device__ __forceinline__ float hi_f(float v) {
    return __half2float(__float2half_rn(v));
}
__device__ __forceinline__ unsigned packh2(float a, float b) {
    __half2 h = __halves2half2(__float2half_rn(a), __float2half_rn(b));
    return *reinterpret_cast<unsigned*>(&h);
}
__device__ __forceinline__ unsigned a_pair(const float* row, int k) {
    return packh2(-2.f * hi_f(row[k]), -2.f * hi_f(row[k + 1]));
}
__device__ __forceinline__ unsigned b_pair(const float* row, int k) {
    return packh2(hi_f(row[k]), hi_f(row[k + 1]));
}

// prep B + norms: stage 128 rows coalesced into smem, then pack frags + exact norms.
// frag layout per tile: [nf16][ks4][lane32] uint2 = {b(k0,k0+1), b(k0+8,k0+9)}.
__global__ __launch_bounds__(256) void prep_feats(const float* __restrict__ rowsBase,
                                                  int tileBase, int rowBase) {
    __shared__ float stage[128 * KD];
    const float4* bsrc = (const float4*)rowsBase + (size_t)blockIdx.x * 2048;
    float4* st4 = (float4*)stage;
#pragma unroll
    for (int i = 0; i < 8; i++)
        st4[threadIdx.x + 256 * i] = bsrc[threadIdx.x + 256 * i];
    __syncthreads();

    if (threadIdx.x < 128) {
        const float* r = stage + threadIdx.x * KD;
        float s = 0.f;
#pragma unroll
        for (int k = 0; k < KD; k++)
            s = __fadd_rn(s, __fmul_rn(r[k], r[k]));
        g_norms[rowBase + blockIdx.x * 128 + threadIdx.x] = s;
    }

    uint2* dst = g_Bbuf + (size_t)(tileBase + blockIdx.x) * 2048;
#pragma unroll
    for (int i = 0; i < 8; i++) {
        int e = threadIdx.x + 256 * i;
        int nf = e >> 7, ks = (e >> 5) & 3, lane = e & 31;
        const float* row = stage + (size_t)(nf * 8 + (lane >> 2)) * KD;
        int k0 = ks * 16 + (lane & 3) * 2;
        uint2 o;
        o.x = b_pair(row, k0);
        o.y = b_pair(row, k0 + 8);
        dst[e] = o;
    }
}

// prep A: gather 128 goal rows (optionally via perm) into smem, pack frags.
// [mf8][ks4][lane32] uint4: rows r/(r+8), k-cols (lane&3)*2 in klow/khigh.
__global__ __launch_bounds__(256) void prep_goals(const float* __restrict__ rows,
                                                  int usePerm) {
    __shared__ float stage[128 * KD];
    int gbase = blockIdx.x * 128;
    float4* st4 = (float4*)stage;
#pragma unroll
    for (int i = 0; i < 8; i++) {
        int e = threadIdx.x + 256 * i;
        int r = e >> 4, q = e & 15;
        int src = usePerm ? g_perm[gbase + r] : (gbase + r);
        st4[e] = ((const float4*)(rows + (size_t)src * KD))[q];
    }
    __syncthreads();

    uint4* dst = g_Abuf + blockIdx.x * 1024;
#pragma unroll
    for (int i = 0; i < 4; i++) {
        int e = threadIdx.x + 256 * i;
        int mf = e >> 7, ks = (e >> 5) & 3, lane = e & 31;
        int rloc = mf * 16 + (lane >> 2);
        int k0 = ks * 16 + (lane & 3) * 2;
        const float* r0 = stage + (size_t)rloc * KD;
        const float* r1 = stage + (size_t)(rloc + 8) * KD;
        uint4 o;
        o.x = a_pair(r0, k0);     o.y = a_pair(r1, k0);
        o.z = a_pair(r0, k0 + 8); o.w = a_pair(r1, k0 + 8);
        dst[e] = o;
    }
}

// ---------------- low-level helpers ----------------
__device__ __forceinline__ unsigned smem_u32(const void* p) {
    unsigned a;
    asm("{ .reg .u64 t; cvta.to.shared.u64 t, %1; cvt.u32.u64 %0, t; }"
        : "=r"(a) : "l"(p));
    return a;
}
__device__ __forceinline__ void cp_async16(unsigned s, const void* g) {
    asm volatile("cp.async.cg.shared.global [%0], [%1], 16;" :: "r"(s), "l"(g));
}
__device__ __forceinline__ void cp_commit() {
    asm volatile("cp.async.commit_group;" ::: "memory");
}
__device__ __forceinline__ void cp_wait0() {
    asm volatile("cp.async.wait_group 0;" ::: "memory");
}
__device__ __forceinline__ void cp_wait1() {
    asm volatile("cp.async.wait_group 1;" ::: "memory");
}
__device__ __forceinline__ void mma16816(float* d, uint4 a, uint2 b) {
    asm volatile(
        "mma.sync.aligned.m16n8k16.row.col.f32.f16.f16.f32 "
        "{%0,%1,%2,%3}, {%4,%5,%6,%7}, {%8,%9}, {%0,%1,%2,%3};"
        : "+f"(d[0]), "+f"(d[1]), "+f"(d[2]), "+f"(d[3])
        : "r"(a.x), "r"(a.y), "r"(a.z), "r"(a.w), "r"(b.x), "r"(b.y));
}
__device__ __forceinline__ unsigned fkey(float f) {
    unsigned u = __float_as_uint(f);
    return (u & 0x80000000u) ? ~u : (u | 0x80000000u);
}
__device__ __forceinline__ void top3_ins(float v, int idx, float* bv, int* bi) {
    if (v < bv[2]) {
        if (v < bv[1]) {
            bv[2] = bv[1]; bi[2] = bi[1];
            if (v < bv[0]) {
                bv[1] = bv[0]; bi[1] = bi[0];
                bv[0] = v; bi[0] = idx;
            } else { bv[1] = v; bi[1] = idx; }
        } else { bv[2] = v; bi[2] = idx; }
    }
}

__device__ __forceinline__ void issue_tile(unsigned sB, unsigned sN,
                                           int tileIdx, int buf, int tid) {
    const uint4* src = (const uint4*)(g_Bbuf + (size_t)tileIdx * 2048);
    unsigned d = sB + (unsigned)buf * ASZ;
#pragma unroll
    for (int j = 0; j < 4; j++)
        cp_async16(d + (unsigned)(tid + 256 * j) * 16, src + tid + 256 * j);
    if (tid < 32)
        cp_async16(sN + (unsigned)buf * 512 + tid * 16,
                   &g_norms[tileIdx * 128 + tid * 4]);
}

// ---------------- HMMA KNN (K=64): approx key = fn - 2*hi(g)·hi(f) ---------------
// grid (32 m-blocks, 8 splits); block 256 = 8 warps (4m x 2n).
// Warp (wm,wn): goals [wm*32,+32), feats strip [wn*64,+64). Single pass, 4 ks-steps.
// Candidate slots keyed by (split, wn); exact fp32 rescore downstream fixes approx.
__global__ __launch_bounds__(256, 2) void mma_knn(int T) {
    extern __shared__ char smem[];
    char* A_s = smem;
    char* B_s = smem + ASZ;
    float* Ns = (float*)(smem + 3 * ASZ);
    unsigned sB = smem_u32(B_s), sN = smem_u32(Ns);
    int tid = threadIdx.x, lane = tid & 31, w = tid >> 5;
    int wm = w & 3, wn = w >> 2;
    int mb = blockIdx.x, split = blockIdx.y;

    {
        const uint4* Asrc = g_Abuf + mb * 1024;
        unsigned sA = smem_u32(A_s);
#pragma unroll
        for (int j = 0; j < 4; j++)
            cp_async16(sA + (unsigned)(tid + 256 * j) * 16, Asrc + tid + 256 * j);
        issue_tile(sB, sN, split * T + 0, 0, tid);
        cp_commit();
        issue_tile(sB, sN, split * T + 1, 1, tid);
        cp_commit();
    }

    float bv[4][3]; int bi[4][3];
#pragma unroll
    for (int r = 0; r < 4; r++)
#pragma unroll
        for (int t = 0; t < 3; t++) { bv[r][t] = 3.402823466e38f; bi[r][t] = 0; }

    for (int t = 0; t < T; t++) {
        if (t < T - 1) cp_wait1(); else cp_wait0();
        __syncthreads();

        const uint4* Af = (const uint4*)A_s;
        const uint2* Bf = (const uint2*)(B_s + (t & 1) * ASZ);
        const float* fn = Ns + (t & 1) * 128;
        int tileIdx = split * T + t;

        float acc[2][8][4];
#pragma unroll
        for (int i = 0; i < 2; i++)
#pragma unroll
            for (int q = 0; q < 8; q++)
#pragma unroll
                for (int e = 0; e < 4; e++) acc[i][q][e] = 0.f;

#pragma unroll
        for (int ks = 0; ks < 4; ks++) {
            uint4 a0 = Af[((wm * 2 + 0) * 4 + ks) * 32 + lane];
            uint4 a1 = Af[((wm * 2 + 1) * 4 + ks) * 32 + lane];
#pragma unroll
            for (int q = 0; q < 8; q++) {
                uint2 b = Bf[((wn * 8 + q) * 4 + ks) * 32 + lane];
                mma16816(acc[0][q], a0, b);
                mma16816(acc[1][q], a1, b);
            }
        }

#pragma unroll
        for (int i = 0; i < 2; i++)
#pragma unroll
            for (int q = 0; q < 8; q++) {
                int cb = wn * 64 + q * 8 + (lane & 3) * 2;
                float2 f2 = *(const float2*)(fn + cb);
                int gidx = tileIdx * 128 + cb;
                float d0 = acc[i][q][0] + f2.x, d1 = acc[i][q][1] + f2.y;
                if (fminf(d0, d1) < bv[i*2][2]) {
                    top3_ins(d0, gidx,     bv[i*2], bi[i*2]);
                    top3_ins(d1, gidx + 1, bv[i*2], bi[i*2]);
                }
                float d2 = acc[i][q][2] + f2.x, d3 = acc[i][q][3] + f2.y;
                if (fminf(d2, d3) < bv[i*2+1][2]) {
                    top3_ins(d2, gidx,     bv[i*2+1], bi[i*2+1]);
                    top3_ins(d3, gidx + 1, bv[i*2+1], bi[i*2+1]);
                }
            }
        __syncthreads();
        if (t + 2 < T) {
            issue_tile(sB, sN, split * T + t + 2, t & 1, tid);
            cp_commit();
        }
    }

    // quad merge: 12 candidates per goal row -> top-4, slot keyed by (split, wn)
#pragma unroll
    for (int rr = 0; rr < 4; rr++) {
        ull cand[3];
#pragma unroll
        for (int t3 = 0; t3 < 3; t3++)
            cand[t3] = ((ull)fkey(bv[rr][t3]) << 32) | (unsigned)bi[rr][t3];
        int pos = 0;
        int goal = mb * 128 + wm * 32 + (rr >> 1) * 16 + (rr & 1) * 8 + (lane >> 2);
#pragma unroll
        for (int t4 = 0; t4 < 4; t4++) {
            ull cur = (pos < 3) ? cand[pos] : ~0ull;
            ull m = cur;
            ull o1 = __shfl_xor_sync(0xffffffffu, m, 1); if (o1 < m) m = o1;
            ull o2 = __shfl_xor_sync(0xffffffffu, m, 2); if (o2 < m) m = o2;
            if (cur == m) pos++;
            if ((lane & 3) == 0)
                g_cand[goal * 64 + (split * 2 + wn) * 4 + t4] =
                    (int)(m & 0xffffffffu);
        }
    }
}

// ---------------- exact rescore: fp32 d2 over 64 candidates, top-3, mean ---------
__global__ void rescore_k(const float* __restrict__ rows, int usePerm,
                          float* __restrict__ outp) {
    __shared__ float gr[8][64];
    int w = threadIdx.x >> 5, lane = threadIdx.x & 31;
    int g = blockIdx.x * 8 + w;
    int gsrc = usePerm ? g_perm[g] : g;
    const float* grow = rows + (size_t)gsrc * KD;
    gr[w][lane] = grow[lane];
    gr[w][lane + 32] = grow[lane + 32];
    __syncwarp();
    float gn = g_norms[gsrc];

    ull key[2];
#pragma unroll
    for (int ci = 0; ci < 2; ci++) {
        int cand = g_cand[g * 64 + ci * 32 + lane];
        const float4* f4 = (const float4*)(rows + (size_t)cand * KD);
        float dot = 0.f;
#pragma unroll
        for (int k4 = 0; k4 < 16; k4++) {
            float4 v = f4[k4];
            dot = fmaf(gr[w][k4 * 4 + 0], v.x, dot);
            dot = fmaf(gr[w][k4 * 4 + 1], v.y, dot);
            dot = fmaf(gr[w][k4 * 4 + 2], v.z, dot);
            dot = fmaf(gr[w][k4 * 4 + 3], v.w, dot);
        }
        float d2 = fmaf(-2.f, dot, gn + g_norms[cand]);
        key[ci] = ((ull)fkey(d2) << 32) | (unsigned)cand;
    }
    if (key[1] < key[0]) { ull tmp = key[0]; key[0] = key[1]; key[1] = tmp; }

    int ids[3]; int pos = 0;
#pragma unroll
    for (int t = 0; t < 3; t++) {
        ull cur = (pos == 0) ? key[0] : ((pos == 1) ? key[1] : ~0ull);
        ull m = cur;
        for (int off = 16; off; off >>= 1) {
            ull o = __shfl_xor_sync(0xffffffffu, m, off);
            if (o < m) m = o;
        }
        if (cur == m) pos++;
        ids[t] = (int)(m & 0xffffffffu);
    }
    const float* r0 = rows + (size_t)ids[0] * KD;
    const float* r1 = rows + (size_t)ids[1] * KD;
    const float* r2 = rows + (size_t)ids[2] * KD;
#pragma unroll
    for (int d = lane; d < KD; d += 32)
        outp[(size_t)g * KD + d] = ((r0[d] + r1[d]) + r2[d]) / 3.0f;
}

// ---------------- orchestration ----------------
extern "C" void kernel_launch(void* const* d_in, const int* in_sizes, int n_in,
                              void* d_out, int out_size) {
    const float* x = (const float*)d_in[0];   // [4096, 64]
    float* out = (float*)d_out;               // [12288, 64]

    const int MMA_SMEM = 3 * ASZ + 1024;      // 50176
    cudaFuncSetAttribute(mma_knn, cudaFuncAttributeMaxDynamicSharedMemorySize,
                         MMA_SMEM);

    cudaMemcpyAsync(out, x, (size_t)4096 * KD * sizeof(float),
                    cudaMemcpyDeviceToDevice);

    // ---- step 1: goals = feats = rows 0..4095 (8 splits x 4 tiles) ----
    prep_feats<<<32, 256>>>(out, 0, 0);                           // 1 (+ norms)
    prep_goals<<<32, 256>>>(out, 0);                              // 2
    keys_k<<<NPTS / 512, 512>>>();                                // 3 (indep)
    mma_knn<<<dim3(32, 8), 256, MMA_SMEM>>>(4);                   // 4 (ncu slot)
    rank_k<<<dim3(NPTS / 256, 2, NPTS / SEG), 256>>>();           // 5
    compose_k<<<NPTS / 512, 512>>>();                             // 6
    rescore_k<<<512, 256>>>(out, 0, out + (size_t)4096 * KD);     // 7

    // ---- step 2: feats = rows 0..8191 (8 splits x 8 tiles), goals = perm ----
    prep_feats<<<32, 256>>>(out + (size_t)4096 * KD, 32, 4096);
    prep_goals<<<32, 256>>>(out, 1);
    mma_knn<<<dim3(32, 8), 256, MMA_SMEM>>>(8);
    rescore_k<<<512, 256>>>(out, 1, out + (size_t)8192 * KD);
}